// round 5
// baseline (speedup 1.0000x reference)
#include <cuda_runtime.h>
#include <cuda_fp16.h>
#include <cstdint>
#include <cstddef>

// Problem constants
constexpr int H_   = 32;
constexpr int D_   = 128;
constexpr int HID_ = 4096;   // H*D
constexpr int B_   = 4;
constexpr int S_   = 1024;
constexpr int T_   = 4096;   // B*S
constexpr float SCALE_ = 0.08838834764831845f;  // D^-0.5

// Scratch (allocation-free rule: __device__ globals)
__device__ float g_qkv[(size_t)T_ * 3 * HID_];   // [T, 3*HID]
// GEMM fp16 split operands
__device__ __half g_Ah[(size_t)T_ * HID_];       // A hi, row-major [M][K]
__device__ __half g_Al[(size_t)T_ * HID_];       // A lo
__device__ __half g_Bh[(size_t)HID_ * 3 * HID_]; // B^T hi, row-major [N][K]
__device__ __half g_Bl[(size_t)HID_ * 3 * HID_]; // B^T lo
// Attention fp16 operands (written by rope kernel)
__device__ __half g_Qh[(size_t)T_ * HID_];
__device__ __half g_Ql[(size_t)T_ * HID_];
__device__ __half g_Kh[(size_t)T_ * HID_];
__device__ __half g_Kl[(size_t)T_ * HID_];
__device__ __half g_Vh[(size_t)T_ * HID_];
__device__ __half g_Vl[(size_t)T_ * HID_];

// ---------------------------------------------------------------------------
// helpers
// ---------------------------------------------------------------------------
__device__ __forceinline__ uint32_t smem_u32(const void* p) {
    uint32_t a;
    asm("{ .reg .u64 t; cvta.to.shared.u64 t, %1; cvt.u32.u64 %0, t; }"
        : "=r"(a) : "l"(p));
    return a;
}
__device__ __forceinline__ void cp16(uint32_t dst, const void* src) {
    asm volatile("cp.async.cg.shared.global [%0], [%1], 16;" :: "r"(dst), "l"(src));
}
__device__ __forceinline__ void cp_commit() { asm volatile("cp.async.commit_group;"); }
template<int Ngrp> __device__ __forceinline__ void cp_wait() {
    asm volatile("cp.async.wait_group %0;" :: "n"(Ngrp));
}
__device__ __forceinline__ void ldsm4(uint32_t* r, uint32_t addr) {
    asm volatile("ldmatrix.sync.aligned.m8n8.x4.shared.b16 {%0,%1,%2,%3}, [%4];"
                 : "=r"(r[0]), "=r"(r[1]), "=r"(r[2]), "=r"(r[3]) : "r"(addr));
}
__device__ __forceinline__ void ldsm4t(uint32_t* r, uint32_t addr) {
    asm volatile("ldmatrix.sync.aligned.m8n8.x4.trans.shared.b16 {%0,%1,%2,%3}, [%4];"
                 : "=r"(r[0]), "=r"(r[1]), "=r"(r[2]), "=r"(r[3]) : "r"(addr));
}
__device__ __forceinline__ void mma16816(float* c, const uint32_t* a, const uint32_t* b) {
    asm volatile("mma.sync.aligned.m16n8k16.row.col.f32.f16.f16.f32 "
                 "{%0,%1,%2,%3}, {%4,%5,%6,%7}, {%8,%9}, {%0,%1,%2,%3};"
                 : "+f"(c[0]), "+f"(c[1]), "+f"(c[2]), "+f"(c[3])
                 : "r"(a[0]), "r"(a[1]), "r"(a[2]), "r"(a[3]), "r"(b[0]), "r"(b[1]));
}
__device__ __forceinline__ uint32_t packh2(float x, float y) {
    __half2 p = __halves2half2(__float2half_rn(x), __float2half_rn(y));
    return *(uint32_t*)&p;
}

// ---------------------------------------------------------------------------
// convA: fp32 row-major -> fp16 hi/lo row-major (8 elems / thread)
// ---------------------------------------------------------------------------
__global__ __launch_bounds__(256)
void convA_kernel(const float* __restrict__ src, __half* __restrict__ hi,
                  __half* __restrict__ lo)
{
    size_t base = ((size_t)blockIdx.x * 256 + threadIdx.x) * 8;
    const float4* s = (const float4*)(src + base);
    float4 a = s[0], b = s[1];
    float x[8] = {a.x, a.y, a.z, a.w, b.x, b.y, b.z, b.w};
    uint4 uh, ul;
    uint32_t* ph = (uint32_t*)&uh;
    uint32_t* pl = (uint32_t*)&ul;
    #pragma unroll
    for (int j = 0; j < 4; j++) {
        __half h0 = __float2half_rn(x[2*j]), h1 = __float2half_rn(x[2*j+1]);
        ph[j] = packh2(x[2*j], x[2*j+1]);
        pl[j] = packh2(x[2*j]   - __half2float(h0),
                       x[2*j+1] - __half2float(h1));
    }
    *(uint4*)(hi + base) = uh;
    *(uint4*)(lo + base) = ul;
}

// ---------------------------------------------------------------------------
// convT: fp32 [K, N] -> transposed fp16 hi/lo [N, K].  32x32 smem tiles.
// ---------------------------------------------------------------------------
__global__ __launch_bounds__(256)
void convT_kernel(const float* __restrict__ w, __half* __restrict__ hi,
                  __half* __restrict__ lo, int K, int N)
{
    __shared__ float t[32][33];
    const int k0 = blockIdx.x * 32, n0 = blockIdx.y * 32;
    const int tx = threadIdx.x & 31, ty = threadIdx.x >> 5;
    #pragma unroll
    for (int i = 0; i < 32; i += 8)
        t[ty + i][tx] = w[(size_t)(k0 + ty + i) * N + n0 + tx];
    __syncthreads();
    #pragma unroll
    for (int i = 0; i < 32; i += 8) {
        float x = t[tx][ty + i];
        __half h = __float2half_rn(x);
        __half l = __float2half_rn(x - __half2float(h));
        size_t o = (size_t)(n0 + ty + i) * K + k0 + tx;
        hi[o] = h;
        lo[o] = l;
    }
}

// ---------------------------------------------------------------------------
// HGEMM: C[M,N] = A @ B, fp16 hi/lo split (3 MMA terms), fp32 accum.
// A: [M,K] hi/lo row-major.  B: [N,K] hi/lo row-major (B^T).
// 256x128 CTA tile, BK=32, 3-stage cp.async, 8 warps (4x2), warp tile 64x64.
// smem/stage: Ah 16K | Al 16K | Bh 8K | Bl 8K = 48K
// ---------------------------------------------------------------------------
constexpr int G_STAGE = 49152;
constexpr int G_SMEM  = 3 * G_STAGE;      // 144 KB

__global__ __launch_bounds__(256)
void hgemm_kernel(const __half* __restrict__ Ah, const __half* __restrict__ Al,
                  const __half* __restrict__ Bh, const __half* __restrict__ Bl,
                  float* __restrict__ C, int N, int K)
{
    extern __shared__ char sm[];
    const int tid  = threadIdx.x;
    const int wid  = tid >> 5, lane = tid & 31;
    const int bm = blockIdx.x, bn = blockIdx.y;
    const int wm = (wid >> 1) * 64;       // warp row offset (4 groups)
    const int wn = (wid & 1) * 64;        // warp col offset (2 groups)
    const int KT = K / 32;
    const uint32_t sb = smem_u32(sm);

    const __half* aop[2] = {Ah + (size_t)bm * 256 * K, Al + (size_t)bm * 256 * K};
    const __half* bop[2] = {Bh + (size_t)bn * 128 * K, Bl + (size_t)bn * 128 * K};

    // prefetch one BK=32 stage: A 2x1024 chunks, B 2x512 chunks (12 cp16/thread)
    auto prefetch = [&](int kt) {
        const uint32_t st = sb + (kt % 3) * G_STAGE;
        #pragma unroll
        for (int op = 0; op < 2; op++) {
            #pragma unroll
            for (int j = 0; j < 4; j++) {
                int ch = j * 256 + tid;
                int row = ch >> 2, c = ch & 3;
                cp16(st + op * 16384 + row * 64 + ((c ^ (row & 3)) << 4),
                     aop[op] + (size_t)row * K + kt * 32 + c * 8);
            }
        }
        #pragma unroll
        for (int op = 0; op < 2; op++) {
            #pragma unroll
            for (int j = 0; j < 2; j++) {
                int ch = j * 256 + tid;
                int row = ch >> 2, c = ch & 3;
                cp16(st + 32768 + op * 8192 + row * 64 + ((c ^ (row & 3)) << 4),
                     bop[op] + (size_t)row * K + kt * 32 + c * 8);
            }
        }
        cp_commit();
    };

    prefetch(0);
    if (KT > 1) prefetch(1);

    float acc[4][8][4] = {};

    for (int kt = 0; kt < KT; kt++) {
        __syncthreads();                       // everyone done with buf (kt+2)%3
        if (kt + 2 < KT) prefetch(kt + 2);
        if (kt + 2 < KT)      cp_wait<2>();
        else if (kt + 1 < KT) cp_wait<1>();
        else                  cp_wait<0>();
        __syncthreads();                       // stage kt visible

        const uint32_t st = sb + (kt % 3) * G_STAGE;
        #pragma unroll
        for (int ks = 0; ks < 2; ks++) {       // two k16 steps per BK=32
            uint32_t bhf[4][4], blf[4][4];
            #pragma unroll
            for (int p = 0; p < 4; p++) {
                int n = wn + p * 16 + ((lane >> 4) << 3) + (lane & 7);
                int c = ks * 2 + ((lane >> 3) & 1);
                uint32_t addr = st + 32768 + n * 64 + ((c ^ (n & 3)) << 4);
                ldsm4(bhf[p], addr);
                ldsm4(blf[p], addr + 8192);
            }
            #pragma unroll
            for (int mt = 0; mt < 4; mt++) {
                uint32_t ahf[4], alf[4];
                int row = wm + mt * 16 + (lane & 15);
                int c   = ks * 2 + (lane >> 4);
                uint32_t addr = st + row * 64 + ((c ^ (row & 3)) << 4);
                ldsm4(ahf, addr);
                ldsm4(alf, addr + 16384);
                #pragma unroll
                for (int nt = 0; nt < 8; nt++) {
                    const uint32_t* bh2 = &bhf[nt >> 1][(nt & 1) * 2];
                    const uint32_t* bl2 = &blf[nt >> 1][(nt & 1) * 2];
                    mma16816(acc[mt][nt], ahf, bh2);
                    mma16816(acc[mt][nt], ahf, bl2);
                    mma16816(acc[mt][nt], alf, bh2);
                }
            }
        }
    }

    // epilogue
    #pragma unroll
    for (int mt = 0; mt < 4; mt++)
        #pragma unroll
        for (int nt = 0; nt < 8; nt++) {
            int r0  = bm * 256 + wm + mt * 16 + (lane >> 2);
            int col = bn * 128 + wn + nt * 8 + (lane & 3) * 2;
            *(float2*)(C + (size_t)r0 * N + col) =
                make_float2(acc[mt][nt][0], acc[mt][nt][1]);
            *(float2*)(C + (size_t)(r0 + 8) * N + col) =
                make_float2(acc[mt][nt][2], acc[mt][nt][3]);
        }
}

// ---------------------------------------------------------------------------
// RoPE + cache scatter + fp16 hi/lo emit for attention operands.
// ---------------------------------------------------------------------------
__global__ __launch_bounds__(64)
void rope_cache_kernel(const float* __restrict__ cosT,
                       const float* __restrict__ sinT,
                       float* __restrict__ kc,
                       float* __restrict__ vc)
{
    const int th = blockIdx.x;
    const int t = th >> 5;
    const int h = th & 31;
    const int i = threadIdx.x;

    const float c = cosT[t * 64 + i];
    const float s = sinT[t * 64 + i];

    const size_t base = (size_t)t * 3 * HID_ + h * D_;
    const size_t co   = (size_t)t * HID_ + h * D_ + 2 * i;

    float q1 = g_qkv[base + 2 * i], q2 = g_qkv[base + 2 * i + 1];
    float r1 = q1 * c - q2 * s, r2 = q2 * c + q1 * s;
    {
        __half h0 = __float2half_rn(r1), h1 = __float2half_rn(r2);
        *(uint32_t*)(g_Qh + co) = packh2(r1, r2);
        *(uint32_t*)(g_Ql + co) = packh2(r1 - __half2float(h0), r2 - __half2float(h1));
    }
    float k1 = g_qkv[base + HID_ + 2 * i], k2 = g_qkv[base + HID_ + 2 * i + 1];
    float kr1 = k1 * c - k2 * s, kr2 = k2 * c + k1 * s;
    kc[co]     = kr1;
    kc[co + 1] = kr2;
    {
        __half h0 = __float2half_rn(kr1), h1 = __float2half_rn(kr2);
        *(uint32_t*)(g_Kh + co) = packh2(kr1, kr2);
        *(uint32_t*)(g_Kl + co) = packh2(kr1 - __half2float(h0), kr2 - __half2float(h1));
    }
    float v1 = g_qkv[base + 2 * HID_ + 2 * i], v2 = g_qkv[base + 2 * HID_ + 2 * i + 1];
    vc[co]     = v1;
    vc[co + 1] = v2;
    {
        __half h0 = __float2half_rn(v1), h1 = __float2half_rn(v2);
        *(uint32_t*)(g_Vh + co) = packh2(v1, v2);
        *(uint32_t*)(g_Vl + co) = packh2(v1 - __half2float(h0), v2 - __half2float(h1));
    }
}

// ---------------------------------------------------------------------------
// Flash attention on mma.sync, fp16 hi/lo split (unchanged from round 4).
// ---------------------------------------------------------------------------
constexpr int FA_ST = 34816;          // stage size in halfs (4 * 8704)
constexpr int FA_SMEM_BYTES = (34816 + 2 * 34816) * 2;   // 208896

__global__ __launch_bounds__(256, 1)
void fattn_kernel()
{
    extern __shared__ __half fsm[];
    const int tid = threadIdx.x;
    const int wid = tid >> 5, lane = tid & 31;
    const int qt = 7 - blockIdx.x;
    const int h = blockIdx.y, b = blockIdx.z;
    const int t0 = b * S_ + qt * 128;
    const int wrow = wid * 16;
    const uint32_t sb = smem_u32(fsm);

    {
        const __half* qsrc[2] = {g_Qh, g_Ql};
        #pragma unroll
        for (int a = 0; a < 2; a++)
            #pragma unroll
            for (int j = 0; j < 8; j++) {
                int ch = j * 256 + tid;
                int r = ch >> 4, c = ch & 15;
                cp16(sb + (a * 17408 + r * 136 + c * 8) * 2,
                     qsrc[a] + (size_t)(t0 + r) * HID_ + h * D_ + c * 8);
            }
    }

    auto kvload = [&](int kt) {
        const uint32_t dstb = sb + (FA_ST + (kt & 1) * FA_ST) * 2;
        const int tk0 = b * S_ + kt * 64;
        const __half* srcs[4] = {g_Kh, g_Kl, g_Vh, g_Vl};
        #pragma unroll
        for (int a = 0; a < 4; a++)
            #pragma unroll
            for (int j = 0; j < 4; j++) {
                int ch = j * 256 + tid;
                int r = ch >> 4, c = ch & 15;
                cp16(dstb + (a * 8704 + r * 136 + c * 8) * 2,
                     srcs[a] + (size_t)(tk0 + r) * HID_ + h * D_ + c * 8);
            }
        cp_commit();
    };

    const int ktmax = 2 * qt + 1;
    kvload(0);

    float acc[16][4] = {};
    float m_i[2] = {-1e30f, -1e30f};
    float l_i[2] = {0.f, 0.f};

    for (int kt = 0; kt <= ktmax; kt++) {
        if (kt + 1 <= ktmax) { kvload(kt + 1); cp_wait<1>(); }
        else cp_wait<0>();
        __syncthreads();

        const uint32_t stb = sb + (FA_ST + (kt & 1) * FA_ST) * 2;
        const bool active = (kt * 64 <= qt * 128 + wrow + 15);

        if (active) {
            float s[8][4] = {};
            #pragma unroll
            for (int ks = 0; ks < 8; ks++) {
                uint32_t qh[4], ql[4];
                {
                    int row = wrow + (lane & 15);
                    int seg = ks * 16 + 8 * (lane >> 4);
                    uint32_t addr = sb + (row * 136 + seg) * 2;
                    ldsm4(qh, addr);
                    ldsm4(ql, addr + 17408 * 2);
                }
                #pragma unroll
                for (int np = 0; np < 4; np++) {
                    uint32_t kh[4], kl[4];
                    int n = np * 16 + ((lane >> 4) << 3) + (lane & 7);
                    int seg = ks * 16 + 8 * ((lane >> 3) & 1);
                    uint32_t addr = stb + (n * 136 + seg) * 2;
                    ldsm4(kh, addr);
                    ldsm4(kl, addr + 8704 * 2);
                    #pragma unroll
                    for (int half_ = 0; half_ < 2; half_++) {
                        float* st_ = s[np * 2 + half_];
                        const uint32_t* bh2 = &kh[half_ * 2];
                        const uint32_t* bl2 = &kl[half_ * 2];
                        mma16816(st_, qh, bh2);
                        mma16816(st_, qh, bl2);
                        mma16816(st_, ql, bh2);
                    }
                }
            }

            const int rbase = qt * 128 + wrow + (lane >> 2);
            if (kt * 64 + 63 > qt * 128 + wrow) {
                #pragma unroll
                for (int j = 0; j < 8; j++)
                    #pragma unroll
                    for (int cc = 0; cc < 4; cc++) {
                        int colg = kt * 64 + j * 8 + (lane & 3) * 2 + (cc & 1);
                        int rowg = rbase + (cc >> 1) * 8;
                        if (colg > rowg) s[j][cc] = -1e30f;
                    }
            }
            #pragma unroll
            for (int j = 0; j < 8; j++)
                #pragma unroll
                for (int cc = 0; cc < 4; cc++) s[j][cc] *= SCALE_;

            #pragma unroll
            for (int hr = 0; hr < 2; hr++) {
                float rm = -1e30f;
                #pragma unroll
                for (int j = 0; j < 8; j++)
                    rm = fmaxf(rm, fmaxf(s[j][hr * 2], s[j][hr * 2 + 1]));
                rm = fmaxf(rm, __shfl_xor_sync(0xffffffffu, rm, 1));
                rm = fmaxf(rm, __shfl_xor_sync(0xffffffffu, rm, 2));
                float nm  = fmaxf(m_i[hr], rm);
                float fac = __expf(m_i[hr] - nm);
                m_i[hr] = nm;
                float rs = 0.f;
                #pragma unroll
                for (int j = 0; j < 8; j++) {
                    float p0 = __expf(s[j][hr * 2]     - nm);
                    float p1 = __expf(s[j][hr * 2 + 1] - nm);
                    s[j][hr * 2]     = p0;
                    s[j][hr * 2 + 1] = p1;
                    rs += p0 + p1;
                }
                rs += __shfl_xor_sync(0xffffffffu, rs, 1);
                rs += __shfl_xor_sync(0xffffffffu, rs, 2);
                l_i[hr] = l_i[hr] * fac + rs;
                #pragma unroll
                for (int nt = 0; nt < 16; nt++) {
                    acc[nt][hr * 2]     *= fac;
                    acc[nt][hr * 2 + 1] *= fac;
                }
            }

            uint32_t aH[4][4], aL[4][4];
            #pragma unroll
            for (int ks = 0; ks < 4; ks++) {
                #pragma unroll
                for (int half_ = 0; half_ < 2; half_++) {
                    const float* sj = s[ks * 2 + half_];
                    #pragma unroll
                    for (int rr = 0; rr < 2; rr++) {
                        float x0 = sj[rr * 2], x1 = sj[rr * 2 + 1];
                        __half h0 = __float2half_rn(x0), h1 = __float2half_rn(x1);
                        aH[ks][half_ * 2 + rr] = packh2(x0, x1);
                        aL[ks][half_ * 2 + rr] = packh2(x0 - __half2float(h0),
                                                        x1 - __half2float(h1));
                    }
                }
            }

            #pragma unroll
            for (int ks = 0; ks < 4; ks++) {
                #pragma unroll
                for (int ntp = 0; ntp < 8; ntp++) {
                    uint32_t vh[4], vl[4];
                    int kr = ks * 16 + (lane & 7) + 8 * ((lane >> 3) & 1);
                    int nc = ntp * 16 + 8 * (lane >> 4);
                    uint32_t addr = stb + (17408 + kr * 136 + nc) * 2;
                    ldsm4t(vh, addr);
                    ldsm4t(vl, addr + 8704 * 2);
                    #pragma unroll
                    for (int half_ = 0; half_ < 2; half_++) {
                        float* ot = acc[ntp * 2 + half_];
                        const uint32_t* bh2 = &vh[half_ * 2];
                        const uint32_t* bl2 = &vl[half_ * 2];
                        mma16816(ot, aH[ks], bh2);
                        mma16816(ot, aH[ks], bl2);
                        mma16816(ot, aL[ks], bh2);
                    }
                }
            }
        }
        __syncthreads();
    }

    float inv0 = 1.0f / l_i[0], inv1 = 1.0f / l_i[1];
    #pragma unroll
    for (int nt = 0; nt < 16; nt++) {
        float o0 = acc[nt][0] * inv0, o1 = acc[nt][1] * inv0;
        float o2 = acc[nt][2] * inv1, o3 = acc[nt][3] * inv1;
        size_t col = (size_t)h * D_ + nt * 8 + (lane & 3) * 2;
        size_t r0 = (size_t)(t0 + wrow + (lane >> 2)) * HID_ + col;
        size_t r1 = r0 + 8 * HID_;
        __half ha = __float2half_rn(o0), hb = __float2half_rn(o1);
        __half hc = __float2half_rn(o2), hd = __float2half_rn(o3);
        *(uint32_t*)(g_Ah + r0) = packh2(o0, o1);
        *(uint32_t*)(g_Al + r0) = packh2(o0 - __half2float(ha), o1 - __half2float(hb));
        *(uint32_t*)(g_Ah + r1) = packh2(o2, o3);
        *(uint32_t*)(g_Al + r1) = packh2(o2 - __half2float(hc), o3 - __half2float(hd));
    }
}

// ---------------------------------------------------------------------------
// Launch
// ---------------------------------------------------------------------------
extern "C" void kernel_launch(void* const* d_in, const int* in_sizes, int n_in,
                              void* d_out, int out_size)
{
    const float* hidden = (const float*)d_in[0];
    const float* cosT   = (const float*)d_in[1];
    const float* sinT   = (const float*)d_in[2];
    const float* w_qkv  = (const float*)d_in[3];
    const float* w_o    = (const float*)d_in[4];

    float* out = (float*)d_out;
    float* kc  = out + (size_t)T_ * HID_;
    float* vc  = kc + (size_t)T_ * HID_;

    float* qkvp = nullptr;
    __half *ahp = nullptr, *alp = nullptr, *bhp = nullptr, *blp = nullptr;
    cudaGetSymbolAddress((void**)&qkvp, g_qkv);
    cudaGetSymbolAddress((void**)&ahp, g_Ah);
    cudaGetSymbolAddress((void**)&alp, g_Al);
    cudaGetSymbolAddress((void**)&bhp, g_Bh);
    cudaGetSymbolAddress((void**)&blp, g_Bl);

    cudaFuncSetAttribute(hgemm_kernel, cudaFuncAttributeMaxDynamicSharedMemorySize,
                         G_SMEM);
    cudaFuncSetAttribute(fattn_kernel, cudaFuncAttributeMaxDynamicSharedMemorySize,
                         FA_SMEM_BYTES);

    // 1) convert hidden + w_qkv
    convA_kernel<<<(int)((size_t)T_ * HID_ / 8 / 256), 256>>>(hidden, ahp, alp);
    convT_kernel<<<dim3(HID_ / 32, 3 * HID_ / 32), 256>>>(w_qkv, bhp, blp,
                                                          HID_, 3 * HID_);
    // 2) QKV GEMM -> g_qkv fp32
    hgemm_kernel<<<dim3(T_ / 256, 3 * HID_ / 128), 256, G_SMEM>>>(
        ahp, alp, bhp, blp, qkvp, 3 * HID_, HID_);
    // 3) RoPE + caches + fp16 attention operands
    rope_cache_kernel<<<T_ * H_, 64>>>(cosT, sinT, kc, vc);
    // 4) flash attention (mma.sync) -> g_Ah/g_Al fp16 ctx
    fattn_kernel<<<dim3(S_ / 128, H_, B_), 256, FA_SMEM_BYTES>>>();
    // 5) convert w_o, output projection -> out
    convT_kernel<<<dim3(HID_ / 32, HID_ / 32), 256>>>(w_o, bhp, blp, HID_, HID_);
    hgemm_kernel<<<dim3(T_ / 256, HID_ / 128), 256, G_SMEM>>>(
        ahp, alp, bhp, blp, out, HID_, HID_);
}

// round 6
// speedup vs baseline: 1.1566x; 1.1566x over previous
#include <cuda_runtime.h>
#include <cuda_fp16.h>
#include <cstdint>
#include <cstddef>

// Problem constants
constexpr int H_   = 32;
constexpr int D_   = 128;
constexpr int HID_ = 4096;   // H*D
constexpr int B_   = 4;
constexpr int S_   = 1024;
constexpr int T_   = 4096;   // B*S
constexpr float SCALE_ = 0.08838834764831845f;  // D^-0.5

// Scratch (allocation-free rule: __device__ globals)
__device__ float g_qkv[(size_t)T_ * 3 * HID_];   // [T, 3*HID]
// GEMM fp16 split operands
__device__ __half g_Ah[(size_t)T_ * HID_];       // A hi, row-major [M][K]
__device__ __half g_Al[(size_t)T_ * HID_];       // A lo
__device__ __half g_Bh[(size_t)HID_ * 3 * HID_]; // B^T hi, row-major [N][K]
__device__ __half g_Bl[(size_t)HID_ * 3 * HID_]; // B^T lo
// Attention fp16 operands (written by rope kernel)
__device__ __half g_Qh[(size_t)T_ * HID_];
__device__ __half g_Ql[(size_t)T_ * HID_];
__device__ __half g_Kh[(size_t)T_ * HID_];
__device__ __half g_Kl[(size_t)T_ * HID_];
__device__ __half g_Vh[(size_t)T_ * HID_];
__device__ __half g_Vl[(size_t)T_ * HID_];

// ---------------------------------------------------------------------------
// helpers
// ---------------------------------------------------------------------------
__device__ __forceinline__ uint32_t smem_u32(const void* p) {
    uint32_t a;
    asm("{ .reg .u64 t; cvta.to.shared.u64 t, %1; cvt.u32.u64 %0, t; }"
        : "=r"(a) : "l"(p));
    return a;
}
__device__ __forceinline__ void cp16(uint32_t dst, const void* src) {
    asm volatile("cp.async.cg.shared.global [%0], [%1], 16;" :: "r"(dst), "l"(src));
}
__device__ __forceinline__ void cp_commit() { asm volatile("cp.async.commit_group;"); }
template<int Ngrp> __device__ __forceinline__ void cp_wait() {
    asm volatile("cp.async.wait_group %0;" :: "n"(Ngrp));
}
__device__ __forceinline__ void ldsm4(uint32_t* r, uint32_t addr) {
    asm volatile("ldmatrix.sync.aligned.m8n8.x4.shared.b16 {%0,%1,%2,%3}, [%4];"
                 : "=r"(r[0]), "=r"(r[1]), "=r"(r[2]), "=r"(r[3]) : "r"(addr));
}
__device__ __forceinline__ void ldsm4t(uint32_t* r, uint32_t addr) {
    asm volatile("ldmatrix.sync.aligned.m8n8.x4.trans.shared.b16 {%0,%1,%2,%3}, [%4];"
                 : "=r"(r[0]), "=r"(r[1]), "=r"(r[2]), "=r"(r[3]) : "r"(addr));
}
__device__ __forceinline__ void mma16816(float* c, const uint32_t* a, const uint32_t* b) {
    asm volatile("mma.sync.aligned.m16n8k16.row.col.f32.f16.f16.f32 "
                 "{%0,%1,%2,%3}, {%4,%5,%6,%7}, {%8,%9}, {%0,%1,%2,%3};"
                 : "+f"(c[0]), "+f"(c[1]), "+f"(c[2]), "+f"(c[3])
                 : "r"(a[0]), "r"(a[1]), "r"(a[2]), "r"(a[3]), "r"(b[0]), "r"(b[1]));
}
__device__ __forceinline__ uint32_t packh2(float x, float y) {
    __half2 p = __halves2half2(__float2half_rn(x), __float2half_rn(y));
    return *(uint32_t*)&p;
}

// ---------------------------------------------------------------------------
// convA: fp32 row-major -> fp16 hi/lo row-major (8 elems / thread)
// ---------------------------------------------------------------------------
__global__ __launch_bounds__(256)
void convA_kernel(const float* __restrict__ src, __half* __restrict__ hi,
                  __half* __restrict__ lo)
{
    size_t base = ((size_t)blockIdx.x * 256 + threadIdx.x) * 8;
    const float4* s = (const float4*)(src + base);
    float4 a = s[0], b = s[1];
    float x[8] = {a.x, a.y, a.z, a.w, b.x, b.y, b.z, b.w};
    uint4 uh, ul;
    uint32_t* ph = (uint32_t*)&uh;
    uint32_t* pl = (uint32_t*)&ul;
    #pragma unroll
    for (int j = 0; j < 4; j++) {
        __half h0 = __float2half_rn(x[2*j]), h1 = __float2half_rn(x[2*j+1]);
        ph[j] = packh2(x[2*j], x[2*j+1]);
        pl[j] = packh2(x[2*j]   - __half2float(h0),
                       x[2*j+1] - __half2float(h1));
    }
    *(uint4*)(hi + base) = uh;
    *(uint4*)(lo + base) = ul;
}

// ---------------------------------------------------------------------------
// convT: fp32 [K, N] -> transposed fp16 hi/lo [N, K].  32x32 smem tiles.
// ---------------------------------------------------------------------------
__global__ __launch_bounds__(256)
void convT_kernel(const float* __restrict__ w, __half* __restrict__ hi,
                  __half* __restrict__ lo, int K, int N)
{
    __shared__ float t[32][33];
    const int k0 = blockIdx.x * 32, n0 = blockIdx.y * 32;
    const int tx = threadIdx.x & 31, ty = threadIdx.x >> 5;
    #pragma unroll
    for (int i = 0; i < 32; i += 8)
        t[ty + i][tx] = w[(size_t)(k0 + ty + i) * N + n0 + tx];
    __syncthreads();
    #pragma unroll
    for (int i = 0; i < 32; i += 8) {
        float x = t[tx][ty + i];
        __half h = __float2half_rn(x);
        __half l = __float2half_rn(x - __half2float(h));
        size_t o = (size_t)(n0 + ty + i) * K + k0 + tx;
        hi[o] = h;
        lo[o] = l;
    }
}

// ---------------------------------------------------------------------------
// HGEMM: C[M,N] = A @ B, fp16 hi/lo split (3 MMA terms), fp32 accum.
// A: [M,K] hi/lo row-major.  B: [N,K] hi/lo row-major (B^T).
// 128x128 tile, BK=32, 3-stage cp.async, 8 warps (2x4), warp tile 64x32.
// 96 KB smem/CTA, 2 CTAs/SM, ONE sync per stage.
// ---------------------------------------------------------------------------
constexpr int G_STAGE = 32768;            // Ah 8K | Al 8K | Bh 8K | Bl 8K
constexpr int G_SMEM  = 3 * G_STAGE;      // 96 KB

__global__ __launch_bounds__(256, 2)
void hgemm_kernel(const __half* __restrict__ Ah, const __half* __restrict__ Al,
                  const __half* __restrict__ Bh, const __half* __restrict__ Bl,
                  float* __restrict__ C, int N, int K)
{
    extern __shared__ char sm[];
    const int tid  = threadIdx.x;
    const int wid  = tid >> 5, lane = tid & 31;
    const int bm = blockIdx.x, bn = blockIdx.y;
    const int wm = (wid >> 2) * 64;       // warp row offset
    const int wn = (wid & 3) * 32;        // warp col offset
    const int KT = K / 32;
    const uint32_t sb = smem_u32(sm);

    const __half* aop[2] = {Ah + (size_t)bm * 128 * K, Al + (size_t)bm * 128 * K};
    const __half* bop[2] = {Bh + (size_t)bn * 128 * K, Bl + (size_t)bn * 128 * K};

    auto prefetch = [&](int kt) {
        const uint32_t st = sb + (kt % 3) * G_STAGE;
        #pragma unroll
        for (int op = 0; op < 4; op++) {
            const __half* src = (op < 2) ? aop[op] : bop[op - 2];
            #pragma unroll
            for (int h2 = 0; h2 < 2; h2++) {
                int ch = h2 * 256 + tid;
                int row = ch >> 2, c = ch & 3;
                cp16(st + op * 8192 + row * 64 + ((c ^ (row & 3)) << 4),
                     src + (size_t)row * K + kt * 32 + c * 8);
            }
        }
        cp_commit();
    };

    prefetch(0);
    if (KT > 1) prefetch(1);

    float acc[4][4][4] = {};

    for (int kt = 0; kt < KT; kt++) {
        if (kt + 1 < KT) cp_wait<1>(); else cp_wait<0>();
        __syncthreads();                   // stage kt visible; iter kt-1 reads done
        if (kt + 2 < KT) prefetch(kt + 2); // overwrites buf (kt+2)%3, safe post-sync

        const uint32_t st = sb + (kt % 3) * G_STAGE;
        #pragma unroll
        for (int ks = 0; ks < 2; ks++) {   // two k16 steps per BK=32
            uint32_t ahf[4][4], alf[4][4], bhf[2][4], blf[2][4];
            #pragma unroll
            for (int mt = 0; mt < 4; mt++) {
                int row = wm + mt * 16 + (lane & 15);
                int c   = ks * 2 + (lane >> 4);
                uint32_t addr = st + row * 64 + ((c ^ (row & 3)) << 4);
                ldsm4(ahf[mt], addr);
                ldsm4(alf[mt], addr + 8192);
            }
            #pragma unroll
            for (int p = 0; p < 2; p++) {
                int n = wn + p * 16 + ((lane >> 4) << 3) + (lane & 7);
                int c = ks * 2 + ((lane >> 3) & 1);
                uint32_t addr = st + 16384 + n * 64 + ((c ^ (n & 3)) << 4);
                ldsm4(bhf[p], addr);
                ldsm4(blf[p], addr + 8192);
            }
            #pragma unroll
            for (int mt = 0; mt < 4; mt++)
                #pragma unroll
                for (int nt = 0; nt < 4; nt++) {
                    const uint32_t* bh2 = &bhf[nt >> 1][(nt & 1) * 2];
                    const uint32_t* bl2 = &blf[nt >> 1][(nt & 1) * 2];
                    mma16816(acc[mt][nt], ahf[mt], bh2);
                    mma16816(acc[mt][nt], ahf[mt], bl2);
                    mma16816(acc[mt][nt], alf[mt], bh2);
                }
        }
    }

    #pragma unroll
    for (int mt = 0; mt < 4; mt++)
        #pragma unroll
        for (int nt = 0; nt < 4; nt++) {
            int r0  = bm * 128 + wm + mt * 16 + (lane >> 2);
            int col = bn * 128 + wn + nt * 8 + (lane & 3) * 2;
            *(float2*)(C + (size_t)r0 * N + col) =
                make_float2(acc[mt][nt][0], acc[mt][nt][1]);
            *(float2*)(C + (size_t)(r0 + 8) * N + col) =
                make_float2(acc[mt][nt][2], acc[mt][nt][3]);
        }
}

// ---------------------------------------------------------------------------
// RoPE + cache scatter + fp16 hi/lo emit for attention operands.
// ---------------------------------------------------------------------------
__global__ __launch_bounds__(64)
void rope_cache_kernel(const float* __restrict__ cosT,
                       const float* __restrict__ sinT,
                       float* __restrict__ kc,
                       float* __restrict__ vc)
{
    const int th = blockIdx.x;
    const int t = th >> 5;
    const int h = th & 31;
    const int i = threadIdx.x;

    const float c = cosT[t * 64 + i];
    const float s = sinT[t * 64 + i];

    const size_t base = (size_t)t * 3 * HID_ + h * D_;
    const size_t co   = (size_t)t * HID_ + h * D_ + 2 * i;

    float q1 = g_qkv[base + 2 * i], q2 = g_qkv[base + 2 * i + 1];
    float r1 = q1 * c - q2 * s, r2 = q2 * c + q1 * s;
    {
        __half h0 = __float2half_rn(r1), h1 = __float2half_rn(r2);
        *(uint32_t*)(g_Qh + co) = packh2(r1, r2);
        *(uint32_t*)(g_Ql + co) = packh2(r1 - __half2float(h0), r2 - __half2float(h1));
    }
    float k1 = g_qkv[base + HID_ + 2 * i], k2 = g_qkv[base + HID_ + 2 * i + 1];
    float kr1 = k1 * c - k2 * s, kr2 = k2 * c + k1 * s;
    kc[co]     = kr1;
    kc[co + 1] = kr2;
    {
        __half h0 = __float2half_rn(kr1), h1 = __float2half_rn(kr2);
        *(uint32_t*)(g_Kh + co) = packh2(kr1, kr2);
        *(uint32_t*)(g_Kl + co) = packh2(kr1 - __half2float(h0), kr2 - __half2float(h1));
    }
    float v1 = g_qkv[base + 2 * HID_ + 2 * i], v2 = g_qkv[base + 2 * HID_ + 2 * i + 1];
    vc[co]     = v1;
    vc[co + 1] = v2;
    {
        __half h0 = __float2half_rn(v1), h1 = __float2half_rn(v2);
        *(uint32_t*)(g_Vh + co) = packh2(v1, v2);
        *(uint32_t*)(g_Vl + co) = packh2(v1 - __half2float(h0), v2 - __half2float(h1));
    }
}

// ---------------------------------------------------------------------------
// Flash attention on mma.sync, fp16 hi/lo split (unchanged from round 4).
// ---------------------------------------------------------------------------
constexpr int FA_ST = 34816;          // stage size in halfs (4 * 8704)
constexpr int FA_SMEM_BYTES = (34816 + 2 * 34816) * 2;   // 208896

__global__ __launch_bounds__(256, 1)
void fattn_kernel()
{
    extern __shared__ __half fsm[];
    const int tid = threadIdx.x;
    const int wid = tid >> 5, lane = tid & 31;
    const int qt = 7 - blockIdx.x;
    const int h = blockIdx.y, b = blockIdx.z;
    const int t0 = b * S_ + qt * 128;
    const int wrow = wid * 16;
    const uint32_t sb = smem_u32(fsm);

    {
        const __half* qsrc[2] = {g_Qh, g_Ql};
        #pragma unroll
        for (int a = 0; a < 2; a++)
            #pragma unroll
            for (int j = 0; j < 8; j++) {
                int ch = j * 256 + tid;
                int r = ch >> 4, c = ch & 15;
                cp16(sb + (a * 17408 + r * 136 + c * 8) * 2,
                     qsrc[a] + (size_t)(t0 + r) * HID_ + h * D_ + c * 8);
            }
    }

    auto kvload = [&](int kt) {
        const uint32_t dstb = sb + (FA_ST + (kt & 1) * FA_ST) * 2;
        const int tk0 = b * S_ + kt * 64;
        const __half* srcs[4] = {g_Kh, g_Kl, g_Vh, g_Vl};
        #pragma unroll
        for (int a = 0; a < 4; a++)
            #pragma unroll
            for (int j = 0; j < 4; j++) {
                int ch = j * 256 + tid;
                int r = ch >> 4, c = ch & 15;
                cp16(dstb + (a * 8704 + r * 136 + c * 8) * 2,
                     srcs[a] + (size_t)(tk0 + r) * HID_ + h * D_ + c * 8);
            }
        cp_commit();
    };

    const int ktmax = 2 * qt + 1;
    kvload(0);

    float acc[16][4] = {};
    float m_i[2] = {-1e30f, -1e30f};
    float l_i[2] = {0.f, 0.f};

    for (int kt = 0; kt <= ktmax; kt++) {
        if (kt + 1 <= ktmax) { kvload(kt + 1); cp_wait<1>(); }
        else cp_wait<0>();
        __syncthreads();

        const uint32_t stb = sb + (FA_ST + (kt & 1) * FA_ST) * 2;
        const bool active = (kt * 64 <= qt * 128 + wrow + 15);

        if (active) {
            float s[8][4] = {};
            #pragma unroll
            for (int ks = 0; ks < 8; ks++) {
                uint32_t qh[4], ql[4];
                {
                    int row = wrow + (lane & 15);
                    int seg = ks * 16 + 8 * (lane >> 4);
                    uint32_t addr = sb + (row * 136 + seg) * 2;
                    ldsm4(qh, addr);
                    ldsm4(ql, addr + 17408 * 2);
                }
                #pragma unroll
                for (int np = 0; np < 4; np++) {
                    uint32_t kh[4], kl[4];
                    int n = np * 16 + ((lane >> 4) << 3) + (lane & 7);
                    int seg = ks * 16 + 8 * ((lane >> 3) & 1);
                    uint32_t addr = stb + (n * 136 + seg) * 2;
                    ldsm4(kh, addr);
                    ldsm4(kl, addr + 8704 * 2);
                    #pragma unroll
                    for (int half_ = 0; half_ < 2; half_++) {
                        float* st_ = s[np * 2 + half_];
                        const uint32_t* bh2 = &kh[half_ * 2];
                        const uint32_t* bl2 = &kl[half_ * 2];
                        mma16816(st_, qh, bh2);
                        mma16816(st_, qh, bl2);
                        mma16816(st_, ql, bh2);
                    }
                }
            }

            const int rbase = qt * 128 + wrow + (lane >> 2);
            if (kt * 64 + 63 > qt * 128 + wrow) {
                #pragma unroll
                for (int j = 0; j < 8; j++)
                    #pragma unroll
                    for (int cc = 0; cc < 4; cc++) {
                        int colg = kt * 64 + j * 8 + (lane & 3) * 2 + (cc & 1);
                        int rowg = rbase + (cc >> 1) * 8;
                        if (colg > rowg) s[j][cc] = -1e30f;
                    }
            }
            #pragma unroll
            for (int j = 0; j < 8; j++)
                #pragma unroll
                for (int cc = 0; cc < 4; cc++) s[j][cc] *= SCALE_;

            #pragma unroll
            for (int hr = 0; hr < 2; hr++) {
                float rm = -1e30f;
                #pragma unroll
                for (int j = 0; j < 8; j++)
                    rm = fmaxf(rm, fmaxf(s[j][hr * 2], s[j][hr * 2 + 1]));
                rm = fmaxf(rm, __shfl_xor_sync(0xffffffffu, rm, 1));
                rm = fmaxf(rm, __shfl_xor_sync(0xffffffffu, rm, 2));
                float nm  = fmaxf(m_i[hr], rm);
                float fac = __expf(m_i[hr] - nm);
                m_i[hr] = nm;
                float rs = 0.f;
                #pragma unroll
                for (int j = 0; j < 8; j++) {
                    float p0 = __expf(s[j][hr * 2]     - nm);
                    float p1 = __expf(s[j][hr * 2 + 1] - nm);
                    s[j][hr * 2]     = p0;
                    s[j][hr * 2 + 1] = p1;
                    rs += p0 + p1;
                }
                rs += __shfl_xor_sync(0xffffffffu, rs, 1);
                rs += __shfl_xor_sync(0xffffffffu, rs, 2);
                l_i[hr] = l_i[hr] * fac + rs;
                #pragma unroll
                for (int nt = 0; nt < 16; nt++) {
                    acc[nt][hr * 2]     *= fac;
                    acc[nt][hr * 2 + 1] *= fac;
                }
            }

            uint32_t aH[4][4], aL[4][4];
            #pragma unroll
            for (int ks = 0; ks < 4; ks++) {
                #pragma unroll
                for (int half_ = 0; half_ < 2; half_++) {
                    const float* sj = s[ks * 2 + half_];
                    #pragma unroll
                    for (int rr = 0; rr < 2; rr++) {
                        float x0 = sj[rr * 2], x1 = sj[rr * 2 + 1];
                        __half h0 = __float2half_rn(x0), h1 = __float2half_rn(x1);
                        aH[ks][half_ * 2 + rr] = packh2(x0, x1);
                        aL[ks][half_ * 2 + rr] = packh2(x0 - __half2float(h0),
                                                        x1 - __half2float(h1));
                    }
                }
            }

            #pragma unroll
            for (int ks = 0; ks < 4; ks++) {
                #pragma unroll
                for (int ntp = 0; ntp < 8; ntp++) {
                    uint32_t vh[4], vl[4];
                    int kr = ks * 16 + (lane & 7) + 8 * ((lane >> 3) & 1);
                    int nc = ntp * 16 + 8 * (lane >> 4);
                    uint32_t addr = stb + (17408 + kr * 136 + nc) * 2;
                    ldsm4t(vh, addr);
                    ldsm4t(vl, addr + 8704 * 2);
                    #pragma unroll
                    for (int half_ = 0; half_ < 2; half_++) {
                        float* ot = acc[ntp * 2 + half_];
                        const uint32_t* bh2 = &vh[half_ * 2];
                        const uint32_t* bl2 = &vl[half_ * 2];
                        mma16816(ot, aH[ks], bh2);
                        mma16816(ot, aH[ks], bl2);
                        mma16816(ot, aL[ks], bh2);
                    }
                }
            }
        }
        __syncthreads();
    }

    float inv0 = 1.0f / l_i[0], inv1 = 1.0f / l_i[1];
    #pragma unroll
    for (int nt = 0; nt < 16; nt++) {
        float o0 = acc[nt][0] * inv0, o1 = acc[nt][1] * inv0;
        float o2 = acc[nt][2] * inv1, o3 = acc[nt][3] * inv1;
        size_t col = (size_t)h * D_ + nt * 8 + (lane & 3) * 2;
        size_t r0 = (size_t)(t0 + wrow + (lane >> 2)) * HID_ + col;
        size_t r1 = r0 + 8 * HID_;
        __half ha = __float2half_rn(o0), hb = __float2half_rn(o1);
        __half hc = __float2half_rn(o2), hd = __float2half_rn(o3);
        *(uint32_t*)(g_Ah + r0) = packh2(o0, o1);
        *(uint32_t*)(g_Al + r0) = packh2(o0 - __half2float(ha), o1 - __half2float(hb));
        *(uint32_t*)(g_Ah + r1) = packh2(o2, o3);
        *(uint32_t*)(g_Al + r1) = packh2(o2 - __half2float(hc), o3 - __half2float(hd));
    }
}

// ---------------------------------------------------------------------------
// Launch
// ---------------------------------------------------------------------------
extern "C" void kernel_launch(void* const* d_in, const int* in_sizes, int n_in,
                              void* d_out, int out_size)
{
    const float* hidden = (const float*)d_in[0];
    const float* cosT   = (const float*)d_in[1];
    const float* sinT   = (const float*)d_in[2];
    const float* w_qkv  = (const float*)d_in[3];
    const float* w_o    = (const float*)d_in[4];

    float* out = (float*)d_out;
    float* kc  = out + (size_t)T_ * HID_;
    float* vc  = kc + (size_t)T_ * HID_;

    float* qkvp = nullptr;
    __half *ahp = nullptr, *alp = nullptr, *bhp = nullptr, *blp = nullptr;
    cudaGetSymbolAddress((void**)&qkvp, g_qkv);
    cudaGetSymbolAddress((void**)&ahp, g_Ah);
    cudaGetSymbolAddress((void**)&alp, g_Al);
    cudaGetSymbolAddress((void**)&bhp, g_Bh);
    cudaGetSymbolAddress((void**)&blp, g_Bl);

    cudaFuncSetAttribute(hgemm_kernel, cudaFuncAttributeMaxDynamicSharedMemorySize,
                         G_SMEM);
    cudaFuncSetAttribute(fattn_kernel, cudaFuncAttributeMaxDynamicSharedMemorySize,
                         FA_SMEM_BYTES);

    // 1) convert hidden + w_qkv
    convA_kernel<<<(int)((size_t)T_ * HID_ / 8 / 256), 256>>>(hidden, ahp, alp);
    convT_kernel<<<dim3(HID_ / 32, 3 * HID_ / 32), 256>>>(w_qkv, bhp, blp,
                                                          HID_, 3 * HID_);
    // 2) QKV GEMM -> g_qkv fp32
    hgemm_kernel<<<dim3(T_ / 128, 3 * HID_ / 128), 256, G_SMEM>>>(
        ahp, alp, bhp, blp, qkvp, 3 * HID_, HID_);
    // 3) RoPE + caches + fp16 attention operands
    rope_cache_kernel<<<T_ * H_, 64>>>(cosT, sinT, kc, vc);
    // 4) flash attention (mma.sync) -> g_Ah/g_Al fp16 ctx
    fattn_kernel<<<dim3(S_ / 128, H_, B_), 256, FA_SMEM_BYTES>>>();
    // 5) convert w_o, output projection -> out
    convT_kernel<<<dim3(HID_ / 32, HID_ / 32), 256>>>(w_o, bhp, blp, HID_, HID_);
    hgemm_kernel<<<dim3(T_ / 128, HID_ / 128), 256, G_SMEM>>>(
        ahp, alp, bhp, blp, out, HID_, HID_);
}

// round 7
// speedup vs baseline: 1.5516x; 1.3415x over previous
#include <cuda_runtime.h>
#include <cuda_fp16.h>
#include <cstdint>
#include <cstddef>

// Problem constants
constexpr int H_   = 32;
constexpr int D_   = 128;
constexpr int HID_ = 4096;   // H*D
constexpr int B_   = 4;
constexpr int S_   = 1024;
constexpr int T_   = 4096;   // B*S
constexpr float SCALE_ = 0.08838834764831845f;  // D^-0.5

// Scratch (allocation-free rule: __device__ globals)
__device__ float g_qkv[(size_t)T_ * 3 * HID_];   // [T, 3*HID]
// GEMM fp16 operands (A: hi only — 2-term split drops A-low)
__device__ __half g_Ah[(size_t)T_ * HID_];       // A hi, row-major [M][K]
__device__ __half g_Bh[(size_t)HID_ * 3 * HID_]; // B^T hi, row-major [N][K]
__device__ __half g_Bl[(size_t)HID_ * 3 * HID_]; // B^T lo
// Attention fp16 operands (written by rope kernel; attention stays 3-term)
__device__ __half g_Qh[(size_t)T_ * HID_];
__device__ __half g_Ql[(size_t)T_ * HID_];
__device__ __half g_Kh[(size_t)T_ * HID_];
__device__ __half g_Kl[(size_t)T_ * HID_];
__device__ __half g_Vh[(size_t)T_ * HID_];
__device__ __half g_Vl[(size_t)T_ * HID_];

// ---------------------------------------------------------------------------
// helpers
// ---------------------------------------------------------------------------
__device__ __forceinline__ uint32_t smem_u32(const void* p) {
    uint32_t a;
    asm("{ .reg .u64 t; cvta.to.shared.u64 t, %1; cvt.u32.u64 %0, t; }"
        : "=r"(a) : "l"(p));
    return a;
}
__device__ __forceinline__ void cp16(uint32_t dst, const void* src) {
    asm volatile("cp.async.cg.shared.global [%0], [%1], 16;" :: "r"(dst), "l"(src));
}
__device__ __forceinline__ void cp_commit() { asm volatile("cp.async.commit_group;"); }
template<int Ngrp> __device__ __forceinline__ void cp_wait() {
    asm volatile("cp.async.wait_group %0;" :: "n"(Ngrp));
}
__device__ __forceinline__ void ldsm4(uint32_t* r, uint32_t addr) {
    asm volatile("ldmatrix.sync.aligned.m8n8.x4.shared.b16 {%0,%1,%2,%3}, [%4];"
                 : "=r"(r[0]), "=r"(r[1]), "=r"(r[2]), "=r"(r[3]) : "r"(addr));
}
__device__ __forceinline__ void ldsm4t(uint32_t* r, uint32_t addr) {
    asm volatile("ldmatrix.sync.aligned.m8n8.x4.trans.shared.b16 {%0,%1,%2,%3}, [%4];"
                 : "=r"(r[0]), "=r"(r[1]), "=r"(r[2]), "=r"(r[3]) : "r"(addr));
}
__device__ __forceinline__ void mma16816(float* c, const uint32_t* a, const uint32_t* b) {
    asm volatile("mma.sync.aligned.m16n8k16.row.col.f32.f16.f16.f32 "
                 "{%0,%1,%2,%3}, {%4,%5,%6,%7}, {%8,%9}, {%0,%1,%2,%3};"
                 : "+f"(c[0]), "+f"(c[1]), "+f"(c[2]), "+f"(c[3])
                 : "r"(a[0]), "r"(a[1]), "r"(a[2]), "r"(a[3]), "r"(b[0]), "r"(b[1]));
}
__device__ __forceinline__ uint32_t packh2(float x, float y) {
    __half2 p = __halves2half2(__float2half_rn(x), __float2half_rn(y));
    return *(uint32_t*)&p;
}

// ---------------------------------------------------------------------------
// convH: fp32 row-major -> fp16 hi row-major (8 elems / thread)
// ---------------------------------------------------------------------------
__global__ __launch_bounds__(256)
void convH_kernel(const float* __restrict__ src, __half* __restrict__ hi)
{
    size_t base = ((size_t)blockIdx.x * 256 + threadIdx.x) * 8;
    const float4* s = (const float4*)(src + base);
    float4 a = s[0], b = s[1];
    float x[8] = {a.x, a.y, a.z, a.w, b.x, b.y, b.z, b.w};
    uint4 uh;
    uint32_t* ph = (uint32_t*)&uh;
    #pragma unroll
    for (int j = 0; j < 4; j++) ph[j] = packh2(x[2*j], x[2*j+1]);
    *(uint4*)(hi + base) = uh;
}

// ---------------------------------------------------------------------------
// convT: fp32 [K, N] -> transposed fp16 hi/lo [N, K].  32x32 smem tiles.
// ---------------------------------------------------------------------------
__global__ __launch_bounds__(256)
void convT_kernel(const float* __restrict__ w, __half* __restrict__ hi,
                  __half* __restrict__ lo, int K, int N)
{
    __shared__ float t[32][33];
    const int k0 = blockIdx.x * 32, n0 = blockIdx.y * 32;
    const int tx = threadIdx.x & 31, ty = threadIdx.x >> 5;
    #pragma unroll
    for (int i = 0; i < 32; i += 8)
        t[ty + i][tx] = w[(size_t)(k0 + ty + i) * N + n0 + tx];
    __syncthreads();
    #pragma unroll
    for (int i = 0; i < 32; i += 8) {
        float x = t[tx][ty + i];
        __half h = __float2half_rn(x);
        __half l = __float2half_rn(x - __half2float(h));
        size_t o = (size_t)(n0 + ty + i) * K + k0 + tx;
        hi[o] = h;
        lo[o] = l;
    }
}

// ---------------------------------------------------------------------------
// HGEMM: C[M,N] = A @ B, 2-term split: ah*bh + ah*bl, fp32 accum.
// A: [M,K] hi row-major.  B: [N,K] hi/lo row-major (B^T).
// 128x128 tile, BK=32, 3-stage cp.async, 8 warps (2x4), warp tile 64x32.
// stage: Ah 8K | Bh 8K | Bl 8K = 24KB; 72 KB smem, 2 CTAs/SM, 1 sync/stage.
// ---------------------------------------------------------------------------
constexpr int G_STAGE = 24576;
constexpr int G_SMEM  = 3 * G_STAGE;      // 72 KB

__global__ __launch_bounds__(256, 2)
void hgemm_kernel(const __half* __restrict__ Ah,
                  const __half* __restrict__ Bh, const __half* __restrict__ Bl,
                  float* __restrict__ C, int N, int K)
{
    extern __shared__ char sm[];
    const int tid  = threadIdx.x;
    const int wid  = tid >> 5, lane = tid & 31;
    const int bm = blockIdx.x, bn = blockIdx.y;
    const int wm = (wid >> 2) * 64;       // warp row offset
    const int wn = (wid & 3) * 32;        // warp col offset
    const int KT = K / 32;
    const uint32_t sb = smem_u32(sm);

    const __half* aop = Ah + (size_t)bm * 128 * K;
    const __half* bop[2] = {Bh + (size_t)bn * 128 * K, Bl + (size_t)bn * 128 * K};

    auto prefetch = [&](int kt) {
        const uint32_t st = sb + (kt % 3) * G_STAGE;
        #pragma unroll
        for (int op = 0; op < 3; op++) {
            const __half* src = (op == 0) ? aop : bop[op - 1];
            #pragma unroll
            for (int h2 = 0; h2 < 2; h2++) {
                int ch = h2 * 256 + tid;
                int row = ch >> 2, c = ch & 3;
                cp16(st + op * 8192 + row * 64 + ((c ^ (row & 3)) << 4),
                     src + (size_t)row * K + kt * 32 + c * 8);
            }
        }
        cp_commit();
    };

    prefetch(0);
    if (KT > 1) prefetch(1);

    float acc[4][4][4] = {};

    for (int kt = 0; kt < KT; kt++) {
        if (kt + 1 < KT) cp_wait<1>(); else cp_wait<0>();
        __syncthreads();                   // stage kt visible; iter kt-1 reads done
        if (kt + 2 < KT) prefetch(kt + 2);

        const uint32_t st = sb + (kt % 3) * G_STAGE;
        #pragma unroll
        for (int ks = 0; ks < 2; ks++) {   // two k16 steps per BK=32
            uint32_t ahf[4][4], bhf[2][4], blf[2][4];
            #pragma unroll
            for (int mt = 0; mt < 4; mt++) {
                int row = wm + mt * 16 + (lane & 15);
                int c   = ks * 2 + (lane >> 4);
                ldsm4(ahf[mt], st + row * 64 + ((c ^ (row & 3)) << 4));
            }
            #pragma unroll
            for (int p = 0; p < 2; p++) {
                int n = wn + p * 16 + ((lane >> 4) << 3) + (lane & 7);
                int c = ks * 2 + ((lane >> 3) & 1);
                uint32_t addr = st + 8192 + n * 64 + ((c ^ (n & 3)) << 4);
                ldsm4(bhf[p], addr);
                ldsm4(blf[p], addr + 8192);
            }
            #pragma unroll
            for (int mt = 0; mt < 4; mt++)
                #pragma unroll
                for (int nt = 0; nt < 4; nt++) {
                    const uint32_t* bh2 = &bhf[nt >> 1][(nt & 1) * 2];
                    const uint32_t* bl2 = &blf[nt >> 1][(nt & 1) * 2];
                    mma16816(acc[mt][nt], ahf[mt], bh2);
                    mma16816(acc[mt][nt], ahf[mt], bl2);
                }
        }
    }

    #pragma unroll
    for (int mt = 0; mt < 4; mt++)
        #pragma unroll
        for (int nt = 0; nt < 4; nt++) {
            int r0  = bm * 128 + wm + mt * 16 + (lane >> 2);
            int col = bn * 128 + wn + nt * 8 + (lane & 3) * 2;
            *(float2*)(C + (size_t)r0 * N + col) =
                make_float2(acc[mt][nt][0], acc[mt][nt][1]);
            *(float2*)(C + (size_t)(r0 + 8) * N + col) =
                make_float2(acc[mt][nt][2], acc[mt][nt][3]);
        }
}

// ---------------------------------------------------------------------------
// RoPE + cache scatter + fp16 hi/lo emit for attention operands.
// ---------------------------------------------------------------------------
__global__ __launch_bounds__(64)
void rope_cache_kernel(const float* __restrict__ cosT,
                       const float* __restrict__ sinT,
                       float* __restrict__ kc,
                       float* __restrict__ vc)
{
    const int th = blockIdx.x;
    const int t = th >> 5;
    const int h = th & 31;
    const int i = threadIdx.x;

    const float c = cosT[t * 64 + i];
    const float s = sinT[t * 64 + i];

    const size_t base = (size_t)t * 3 * HID_ + h * D_;
    const size_t co   = (size_t)t * HID_ + h * D_ + 2 * i;

    float q1 = g_qkv[base + 2 * i], q2 = g_qkv[base + 2 * i + 1];
    float r1 = q1 * c - q2 * s, r2 = q2 * c + q1 * s;
    {
        __half h0 = __float2half_rn(r1), h1 = __float2half_rn(r2);
        *(uint32_t*)(g_Qh + co) = packh2(r1, r2);
        *(uint32_t*)(g_Ql + co) = packh2(r1 - __half2float(h0), r2 - __half2float(h1));
    }
    float k1 = g_qkv[base + HID_ + 2 * i], k2 = g_qkv[base + HID_ + 2 * i + 1];
    float kr1 = k1 * c - k2 * s, kr2 = k2 * c + k1 * s;
    kc[co]     = kr1;
    kc[co + 1] = kr2;
    {
        __half h0 = __float2half_rn(kr1), h1 = __float2half_rn(kr2);
        *(uint32_t*)(g_Kh + co) = packh2(kr1, kr2);
        *(uint32_t*)(g_Kl + co) = packh2(kr1 - __half2float(h0), kr2 - __half2float(h1));
    }
    float v1 = g_qkv[base + 2 * HID_ + 2 * i], v2 = g_qkv[base + 2 * HID_ + 2 * i + 1];
    vc[co]     = v1;
    vc[co + 1] = v2;
    {
        __half h0 = __float2half_rn(v1), h1 = __float2half_rn(v2);
        *(uint32_t*)(g_Vh + co) = packh2(v1, v2);
        *(uint32_t*)(g_Vl + co) = packh2(v1 - __half2float(h0), v2 - __half2float(h1));
    }
}

// ---------------------------------------------------------------------------
// Flash attention on mma.sync, fp16 hi/lo split (3-term, unchanged math).
// Epilogue writes ctx as fp16 hi only (O-proj is 2-term).
// ---------------------------------------------------------------------------
constexpr int FA_ST = 34816;          // stage size in halfs (4 * 8704)
constexpr int FA_SMEM_BYTES = (34816 + 2 * 34816) * 2;   // 208896

__global__ __launch_bounds__(256, 1)
void fattn_kernel()
{
    extern __shared__ __half fsm[];
    const int tid = threadIdx.x;
    const int wid = tid >> 5, lane = tid & 31;
    const int qt = 7 - blockIdx.x;
    const int h = blockIdx.y, b = blockIdx.z;
    const int t0 = b * S_ + qt * 128;
    const int wrow = wid * 16;
    const uint32_t sb = smem_u32(fsm);

    {
        const __half* qsrc[2] = {g_Qh, g_Ql};
        #pragma unroll
        for (int a = 0; a < 2; a++)
            #pragma unroll
            for (int j = 0; j < 8; j++) {
                int ch = j * 256 + tid;
                int r = ch >> 4, c = ch & 15;
                cp16(sb + (a * 17408 + r * 136 + c * 8) * 2,
                     qsrc[a] + (size_t)(t0 + r) * HID_ + h * D_ + c * 8);
            }
    }

    auto kvload = [&](int kt) {
        const uint32_t dstb = sb + (FA_ST + (kt & 1) * FA_ST) * 2;
        const int tk0 = b * S_ + kt * 64;
        const __half* srcs[4] = {g_Kh, g_Kl, g_Vh, g_Vl};
        #pragma unroll
        for (int a = 0; a < 4; a++)
            #pragma unroll
            for (int j = 0; j < 4; j++) {
                int ch = j * 256 + tid;
                int r = ch >> 4, c = ch & 15;
                cp16(dstb + (a * 8704 + r * 136 + c * 8) * 2,
                     srcs[a] + (size_t)(tk0 + r) * HID_ + h * D_ + c * 8);
            }
        cp_commit();
    };

    const int ktmax = 2 * qt + 1;
    kvload(0);

    float acc[16][4] = {};
    float m_i[2] = {-1e30f, -1e30f};
    float l_i[2] = {0.f, 0.f};

    for (int kt = 0; kt <= ktmax; kt++) {
        if (kt + 1 <= ktmax) { kvload(kt + 1); cp_wait<1>(); }
        else cp_wait<0>();
        __syncthreads();

        const uint32_t stb = sb + (FA_ST + (kt & 1) * FA_ST) * 2;
        const bool active = (kt * 64 <= qt * 128 + wrow + 15);

        if (active) {
            float s[8][4] = {};
            #pragma unroll
            for (int ks = 0; ks < 8; ks++) {
                uint32_t qh[4], ql[4];
                {
                    int row = wrow + (lane & 15);
                    int seg = ks * 16 + 8 * (lane >> 4);
                    uint32_t addr = sb + (row * 136 + seg) * 2;
                    ldsm4(qh, addr);
                    ldsm4(ql, addr + 17408 * 2);
                }
                #pragma unroll
                for (int np = 0; np < 4; np++) {
                    uint32_t kh[4], kl[4];
                    int n = np * 16 + ((lane >> 4) << 3) + (lane & 7);
                    int seg = ks * 16 + 8 * ((lane >> 3) & 1);
                    uint32_t addr = stb + (n * 136 + seg) * 2;
                    ldsm4(kh, addr);
                    ldsm4(kl, addr + 8704 * 2);
                    #pragma unroll
                    for (int half_ = 0; half_ < 2; half_++) {
                        float* st_ = s[np * 2 + half_];
                        const uint32_t* bh2 = &kh[half_ * 2];
                        const uint32_t* bl2 = &kl[half_ * 2];
                        mma16816(st_, qh, bh2);
                        mma16816(st_, qh, bl2);
                        mma16816(st_, ql, bh2);
                    }
                }
            }

            const int rbase = qt * 128 + wrow + (lane >> 2);
            if (kt * 64 + 63 > qt * 128 + wrow) {
                #pragma unroll
                for (int j = 0; j < 8; j++)
                    #pragma unroll
                    for (int cc = 0; cc < 4; cc++) {
                        int colg = kt * 64 + j * 8 + (lane & 3) * 2 + (cc & 1);
                        int rowg = rbase + (cc >> 1) * 8;
                        if (colg > rowg) s[j][cc] = -1e30f;
                    }
            }
            #pragma unroll
            for (int j = 0; j < 8; j++)
                #pragma unroll
                for (int cc = 0; cc < 4; cc++) s[j][cc] *= SCALE_;

            #pragma unroll
            for (int hr = 0; hr < 2; hr++) {
                float rm = -1e30f;
                #pragma unroll
                for (int j = 0; j < 8; j++)
                    rm = fmaxf(rm, fmaxf(s[j][hr * 2], s[j][hr * 2 + 1]));
                rm = fmaxf(rm, __shfl_xor_sync(0xffffffffu, rm, 1));
                rm = fmaxf(rm, __shfl_xor_sync(0xffffffffu, rm, 2));
                float nm  = fmaxf(m_i[hr], rm);
                float fac = __expf(m_i[hr] - nm);
                m_i[hr] = nm;
                float rs = 0.f;
                #pragma unroll
                for (int j = 0; j < 8; j++) {
                    float p0 = __expf(s[j][hr * 2]     - nm);
                    float p1 = __expf(s[j][hr * 2 + 1] - nm);
                    s[j][hr * 2]     = p0;
                    s[j][hr * 2 + 1] = p1;
                    rs += p0 + p1;
                }
                rs += __shfl_xor_sync(0xffffffffu, rs, 1);
                rs += __shfl_xor_sync(0xffffffffu, rs, 2);
                l_i[hr] = l_i[hr] * fac + rs;
                #pragma unroll
                for (int nt = 0; nt < 16; nt++) {
                    acc[nt][hr * 2]     *= fac;
                    acc[nt][hr * 2 + 1] *= fac;
                }
            }

            uint32_t aH[4][4], aL[4][4];
            #pragma unroll
            for (int ks = 0; ks < 4; ks++) {
                #pragma unroll
                for (int half_ = 0; half_ < 2; half_++) {
                    const float* sj = s[ks * 2 + half_];
                    #pragma unroll
                    for (int rr = 0; rr < 2; rr++) {
                        float x0 = sj[rr * 2], x1 = sj[rr * 2 + 1];
                        __half h0 = __float2half_rn(x0), h1 = __float2half_rn(x1);
                        aH[ks][half_ * 2 + rr] = packh2(x0, x1);
                        aL[ks][half_ * 2 + rr] = packh2(x0 - __half2float(h0),
                                                        x1 - __half2float(h1));
                    }
                }
            }

            #pragma unroll
            for (int ks = 0; ks < 4; ks++) {
                #pragma unroll
                for (int ntp = 0; ntp < 8; ntp++) {
                    uint32_t vh[4], vl[4];
                    int kr = ks * 16 + (lane & 7) + 8 * ((lane >> 3) & 1);
                    int nc = ntp * 16 + 8 * (lane >> 4);
                    uint32_t addr = stb + (17408 + kr * 136 + nc) * 2;
                    ldsm4t(vh, addr);
                    ldsm4t(vl, addr + 8704 * 2);
                    #pragma unroll
                    for (int half_ = 0; half_ < 2; half_++) {
                        float* ot = acc[ntp * 2 + half_];
                        const uint32_t* bh2 = &vh[half_ * 2];
                        const uint32_t* bl2 = &vl[half_ * 2];
                        mma16816(ot, aH[ks], bh2);
                        mma16816(ot, aH[ks], bl2);
                        mma16816(ot, aL[ks], bh2);
                    }
                }
            }
        }
        __syncthreads();
    }

    float inv0 = 1.0f / l_i[0], inv1 = 1.0f / l_i[1];
    #pragma unroll
    for (int nt = 0; nt < 16; nt++) {
        float o0 = acc[nt][0] * inv0, o1 = acc[nt][1] * inv0;
        float o2 = acc[nt][2] * inv1, o3 = acc[nt][3] * inv1;
        size_t col = (size_t)h * D_ + nt * 8 + (lane & 3) * 2;
        size_t r0 = (size_t)(t0 + wrow + (lane >> 2)) * HID_ + col;
        size_t r1 = r0 + 8 * HID_;
        *(uint32_t*)(g_Ah + r0) = packh2(o0, o1);
        *(uint32_t*)(g_Ah + r1) = packh2(o2, o3);
    }
}

// ---------------------------------------------------------------------------
// Launch
// ---------------------------------------------------------------------------
extern "C" void kernel_launch(void* const* d_in, const int* in_sizes, int n_in,
                              void* d_out, int out_size)
{
    const float* hidden = (const float*)d_in[0];
    const float* cosT   = (const float*)d_in[1];
    const float* sinT   = (const float*)d_in[2];
    const float* w_qkv  = (const float*)d_in[3];
    const float* w_o    = (const float*)d_in[4];

    float* out = (float*)d_out;
    float* kc  = out + (size_t)T_ * HID_;
    float* vc  = kc + (size_t)T_ * HID_;

    float* qkvp = nullptr;
    __half *ahp = nullptr, *bhp = nullptr, *blp = nullptr;
    cudaGetSymbolAddress((void**)&qkvp, g_qkv);
    cudaGetSymbolAddress((void**)&ahp, g_Ah);
    cudaGetSymbolAddress((void**)&bhp, g_Bh);
    cudaGetSymbolAddress((void**)&blp, g_Bl);

    cudaFuncSetAttribute(hgemm_kernel, cudaFuncAttributeMaxDynamicSharedMemorySize,
                         G_SMEM);
    cudaFuncSetAttribute(fattn_kernel, cudaFuncAttributeMaxDynamicSharedMemorySize,
                         FA_SMEM_BYTES);

    // 1) convert hidden (hi only) + w_qkv (hi/lo, transposed)
    convH_kernel<<<(int)((size_t)T_ * HID_ / 8 / 256), 256>>>(hidden, ahp);
    convT_kernel<<<dim3(HID_ / 32, 3 * HID_ / 32), 256>>>(w_qkv, bhp, blp,
                                                          HID_, 3 * HID_);
    // 2) QKV GEMM (2-term) -> g_qkv fp32
    hgemm_kernel<<<dim3(T_ / 128, 3 * HID_ / 128), 256, G_SMEM>>>(
        ahp, bhp, blp, qkvp, 3 * HID_, HID_);
    // 3) RoPE + caches + fp16 attention operands
    rope_cache_kernel<<<T_ * H_, 64>>>(cosT, sinT, kc, vc);
    // 4) flash attention (3-term mma.sync) -> ctx fp16 into g_Ah
    fattn_kernel<<<dim3(S_ / 128, H_, B_), 256, FA_SMEM_BYTES>>>();
    // 5) convert w_o, output projection (2-term) -> out
    convT_kernel<<<dim3(HID_ / 32, HID_ / 32), 256>>>(w_o, bhp, blp, HID_, HID_);
    hgemm_kernel<<<dim3(T_ / 128, HID_ / 128), 256, G_SMEM>>>(
        ahp, bhp, blp, out, HID_, HID_);
}

// round 8
// speedup vs baseline: 1.6090x; 1.0369x over previous
#include <cuda_runtime.h>
#include <cuda_fp16.h>
#include <cstdint>
#include <cstddef>

// Problem constants
constexpr int H_   = 32;
constexpr int D_   = 128;
constexpr int HID_ = 4096;   // H*D
constexpr int B_   = 4;
constexpr int S_   = 1024;
constexpr int T_   = 4096;   // B*S
constexpr float SCALE_ = 0.08838834764831845f;  // D^-0.5

// Scratch (allocation-free rule: __device__ globals)
__device__ float g_qkv[(size_t)T_ * 3 * HID_];   // [T, 3*HID]
// GEMM fp16 operands (A: hi only — 2-term split drops A-low)
__device__ __half g_Ah[(size_t)T_ * HID_];       // A hi, row-major [M][K]
__device__ __half g_Bh[(size_t)HID_ * 3 * HID_]; // B^T hi, row-major [N][K]
__device__ __half g_Bl[(size_t)HID_ * 3 * HID_]; // B^T lo
// Attention fp16 operands (written by rope kernel; attention stays 3-term)
__device__ __half g_Qh[(size_t)T_ * HID_];
__device__ __half g_Ql[(size_t)T_ * HID_];
__device__ __half g_Kh[(size_t)T_ * HID_];
__device__ __half g_Kl[(size_t)T_ * HID_];
__device__ __half g_Vh[(size_t)T_ * HID_];
__device__ __half g_Vl[(size_t)T_ * HID_];

// ---------------------------------------------------------------------------
// helpers
// ---------------------------------------------------------------------------
__device__ __forceinline__ uint32_t smem_u32(const void* p) {
    uint32_t a;
    asm("{ .reg .u64 t; cvta.to.shared.u64 t, %1; cvt.u32.u64 %0, t; }"
        : "=r"(a) : "l"(p));
    return a;
}
__device__ __forceinline__ void cp16(uint32_t dst, const void* src) {
    asm volatile("cp.async.cg.shared.global [%0], [%1], 16;" :: "r"(dst), "l"(src));
}
__device__ __forceinline__ void cp_commit() { asm volatile("cp.async.commit_group;"); }
template<int Ngrp> __device__ __forceinline__ void cp_wait() {
    asm volatile("cp.async.wait_group %0;" :: "n"(Ngrp));
}
__device__ __forceinline__ void ldsm4(uint32_t* r, uint32_t addr) {
    asm volatile("ldmatrix.sync.aligned.m8n8.x4.shared.b16 {%0,%1,%2,%3}, [%4];"
                 : "=r"(r[0]), "=r"(r[1]), "=r"(r[2]), "=r"(r[3]) : "r"(addr));
}
__device__ __forceinline__ void ldsm4t(uint32_t* r, uint32_t addr) {
    asm volatile("ldmatrix.sync.aligned.m8n8.x4.trans.shared.b16 {%0,%1,%2,%3}, [%4];"
                 : "=r"(r[0]), "=r"(r[1]), "=r"(r[2]), "=r"(r[3]) : "r"(addr));
}
__device__ __forceinline__ void mma16816(float* c, const uint32_t* a, const uint32_t* b) {
    asm volatile("mma.sync.aligned.m16n8k16.row.col.f32.f16.f16.f32 "
                 "{%0,%1,%2,%3}, {%4,%5,%6,%7}, {%8,%9}, {%0,%1,%2,%3};"
                 : "+f"(c[0]), "+f"(c[1]), "+f"(c[2]), "+f"(c[3])
                 : "r"(a[0]), "r"(a[1]), "r"(a[2]), "r"(a[3]), "r"(b[0]), "r"(b[1]));
}
__device__ __forceinline__ uint32_t packh2(float x, float y) {
    __half2 p = __halves2half2(__float2half_rn(x), __float2half_rn(y));
    return *(uint32_t*)&p;
}

// ---------------------------------------------------------------------------
// convH: fp32 row-major -> fp16 hi row-major (8 elems / thread)
// ---------------------------------------------------------------------------
__global__ __launch_bounds__(256)
void convH_kernel(const float* __restrict__ src, __half* __restrict__ hi)
{
    size_t base = ((size_t)blockIdx.x * 256 + threadIdx.x) * 8;
    const float4* s = (const float4*)(src + base);
    float4 a = s[0], b = s[1];
    float x[8] = {a.x, a.y, a.z, a.w, b.x, b.y, b.z, b.w};
    uint4 uh;
    uint32_t* ph = (uint32_t*)&uh;
    #pragma unroll
    for (int j = 0; j < 4; j++) ph[j] = packh2(x[2*j], x[2*j+1]);
    *(uint4*)(hi + base) = uh;
}

// ---------------------------------------------------------------------------
// convT: fp32 [K, N] -> transposed fp16 hi/lo [N, K].  32x32 smem tiles.
// ---------------------------------------------------------------------------
__global__ __launch_bounds__(256)
void convT_kernel(const float* __restrict__ w, __half* __restrict__ hi,
                  __half* __restrict__ lo, int K, int N)
{
    __shared__ float t[32][33];
    const int k0 = blockIdx.x * 32, n0 = blockIdx.y * 32;
    const int tx = threadIdx.x & 31, ty = threadIdx.x >> 5;
    #pragma unroll
    for (int i = 0; i < 32; i += 8)
        t[ty + i][tx] = w[(size_t)(k0 + ty + i) * N + n0 + tx];
    __syncthreads();
    #pragma unroll
    for (int i = 0; i < 32; i += 8) {
        float x = t[tx][ty + i];
        __half h = __float2half_rn(x);
        __half l = __float2half_rn(x - __half2float(h));
        size_t o = (size_t)(n0 + ty + i) * K + k0 + tx;
        hi[o] = h;
        lo[o] = l;
    }
}

// ---------------------------------------------------------------------------
// HGEMM: C[M,N] = A @ B, 2-term split: ah*bh + ah*bl, fp32 accum.
// A: [M,K] hi row-major.  B: [N,K] hi/lo row-major (B^T).
// 128x128 CTA tile, BK=32, 3-stage cp.async.
// 128 threads = 4 warps (2x2), warp tile 64x64 -> fewer LDSM per MMA.
// stage: Ah 8K | Bh 8K | Bl 8K = 24KB; 72 KB smem, 2 CTAs/SM, 1 sync/stage.
// ---------------------------------------------------------------------------
constexpr int G_STAGE = 24576;
constexpr int G_SMEM  = 3 * G_STAGE;      // 72 KB

__global__ __launch_bounds__(128, 2)
void hgemm_kernel(const __half* __restrict__ Ah,
                  const __half* __restrict__ Bh, const __half* __restrict__ Bl,
                  float* __restrict__ C, int N, int K)
{
    extern __shared__ char sm[];
    const int tid  = threadIdx.x;
    const int wid  = tid >> 5, lane = tid & 31;
    const int bm = blockIdx.x, bn = blockIdx.y;
    const int wm = (wid >> 1) * 64;       // warp row offset
    const int wn = (wid & 1) * 64;        // warp col offset
    const int KT = K / 32;
    const uint32_t sb = smem_u32(sm);

    const __half* aop = Ah + (size_t)bm * 128 * K;
    const __half* bop[2] = {Bh + (size_t)bn * 128 * K, Bl + (size_t)bn * 128 * K};

    // 12 cp16 per thread per stage (128 threads)
    auto prefetch = [&](int kt) {
        const uint32_t st = sb + (kt % 3) * G_STAGE;
        #pragma unroll
        for (int op = 0; op < 3; op++) {
            const __half* src = (op == 0) ? aop : bop[op - 1];
            #pragma unroll
            for (int h4 = 0; h4 < 4; h4++) {
                int ch = h4 * 128 + tid;
                int row = ch >> 2, c = ch & 3;
                cp16(st + op * 8192 + row * 64 + ((c ^ (row & 3)) << 4),
                     src + (size_t)row * K + kt * 32 + c * 8);
            }
        }
        cp_commit();
    };

    prefetch(0);
    if (KT > 1) prefetch(1);

    float acc[4][8][4] = {};

    for (int kt = 0; kt < KT; kt++) {
        if (kt + 1 < KT) cp_wait<1>(); else cp_wait<0>();
        __syncthreads();                   // stage kt visible; iter kt-1 reads done
        if (kt + 2 < KT) prefetch(kt + 2);

        const uint32_t st = sb + (kt % 3) * G_STAGE;
        #pragma unroll
        for (int ks = 0; ks < 2; ks++) {   // two k16 steps per BK=32
            uint32_t ahf[4][4], bhf[4][4], blf[4][4];
            #pragma unroll
            for (int mt = 0; mt < 4; mt++) {
                int row = wm + mt * 16 + (lane & 15);
                int c   = ks * 2 + (lane >> 4);
                ldsm4(ahf[mt], st + row * 64 + ((c ^ (row & 3)) << 4));
            }
            #pragma unroll
            for (int p = 0; p < 4; p++) {
                int n = wn + p * 16 + ((lane >> 4) << 3) + (lane & 7);
                int c = ks * 2 + ((lane >> 3) & 1);
                uint32_t addr = st + 8192 + n * 64 + ((c ^ (n & 3)) << 4);
                ldsm4(bhf[p], addr);
                ldsm4(blf[p], addr + 8192);
            }
            #pragma unroll
            for (int mt = 0; mt < 4; mt++)
                #pragma unroll
                for (int nt = 0; nt < 8; nt++) {
                    const uint32_t* bh2 = &bhf[nt >> 1][(nt & 1) * 2];
                    const uint32_t* bl2 = &blf[nt >> 1][(nt & 1) * 2];
                    mma16816(acc[mt][nt], ahf[mt], bh2);
                    mma16816(acc[mt][nt], ahf[mt], bl2);
                }
        }
    }

    #pragma unroll
    for (int mt = 0; mt < 4; mt++)
        #pragma unroll
        for (int nt = 0; nt < 8; nt++) {
            int r0  = bm * 128 + wm + mt * 16 + (lane >> 2);
            int col = bn * 128 + wn + nt * 8 + (lane & 3) * 2;
            *(float2*)(C + (size_t)r0 * N + col) =
                make_float2(acc[mt][nt][0], acc[mt][nt][1]);
            *(float2*)(C + (size_t)(r0 + 8) * N + col) =
                make_float2(acc[mt][nt][2], acc[mt][nt][3]);
        }
}

// ---------------------------------------------------------------------------
// RoPE + cache scatter + fp16 hi/lo emit for attention operands.
// ---------------------------------------------------------------------------
__global__ __launch_bounds__(64)
void rope_cache_kernel(const float* __restrict__ cosT,
                       const float* __restrict__ sinT,
                       float* __restrict__ kc,
                       float* __restrict__ vc)
{
    const int th = blockIdx.x;
    const int t = th >> 5;
    const int h = th & 31;
    const int i = threadIdx.x;

    const float c = cosT[t * 64 + i];
    const float s = sinT[t * 64 + i];

    const size_t base = (size_t)t * 3 * HID_ + h * D_;
    const size_t co   = (size_t)t * HID_ + h * D_ + 2 * i;

    float q1 = g_qkv[base + 2 * i], q2 = g_qkv[base + 2 * i + 1];
    float r1 = q1 * c - q2 * s, r2 = q2 * c + q1 * s;
    {
        __half h0 = __float2half_rn(r1), h1 = __float2half_rn(r2);
        *(uint32_t*)(g_Qh + co) = packh2(r1, r2);
        *(uint32_t*)(g_Ql + co) = packh2(r1 - __half2float(h0), r2 - __half2float(h1));
    }
    float k1 = g_qkv[base + HID_ + 2 * i], k2 = g_qkv[base + HID_ + 2 * i + 1];
    float kr1 = k1 * c - k2 * s, kr2 = k2 * c + k1 * s;
    kc[co]     = kr1;
    kc[co + 1] = kr2;
    {
        __half h0 = __float2half_rn(kr1), h1 = __float2half_rn(kr2);
        *(uint32_t*)(g_Kh + co) = packh2(kr1, kr2);
        *(uint32_t*)(g_Kl + co) = packh2(kr1 - __half2float(h0), kr2 - __half2float(h1));
    }
    float v1 = g_qkv[base + 2 * HID_ + 2 * i], v2 = g_qkv[base + 2 * HID_ + 2 * i + 1];
    vc[co]     = v1;
    vc[co + 1] = v2;
    {
        __half h0 = __float2half_rn(v1), h1 = __float2half_rn(v2);
        *(uint32_t*)(g_Vh + co) = packh2(v1, v2);
        *(uint32_t*)(g_Vl + co) = packh2(v1 - __half2float(h0), v2 - __half2float(h1));
    }
}

// ---------------------------------------------------------------------------
// Flash attention on mma.sync, fp16 hi/lo split (3-term, unchanged).
// Epilogue writes ctx as fp16 hi only (O-proj is 2-term).
// ---------------------------------------------------------------------------
constexpr int FA_ST = 34816;          // stage size in halfs (4 * 8704)
constexpr int FA_SMEM_BYTES = (34816 + 2 * 34816) * 2;   // 208896

__global__ __launch_bounds__(256, 1)
void fattn_kernel()
{
    extern __shared__ __half fsm[];
    const int tid = threadIdx.x;
    const int wid = tid >> 5, lane = tid & 31;
    const int qt = 7 - blockIdx.x;
    const int h = blockIdx.y, b = blockIdx.z;
    const int t0 = b * S_ + qt * 128;
    const int wrow = wid * 16;
    const uint32_t sb = smem_u32(fsm);

    {
        const __half* qsrc[2] = {g_Qh, g_Ql};
        #pragma unroll
        for (int a = 0; a < 2; a++)
            #pragma unroll
            for (int j = 0; j < 8; j++) {
                int ch = j * 256 + tid;
                int r = ch >> 4, c = ch & 15;
                cp16(sb + (a * 17408 + r * 136 + c * 8) * 2,
                     qsrc[a] + (size_t)(t0 + r) * HID_ + h * D_ + c * 8);
            }
    }

    auto kvload = [&](int kt) {
        const uint32_t dstb = sb + (FA_ST + (kt & 1) * FA_ST) * 2;
        const int tk0 = b * S_ + kt * 64;
        const __half* srcs[4] = {g_Kh, g_Kl, g_Vh, g_Vl};
        #pragma unroll
        for (int a = 0; a < 4; a++)
            #pragma unroll
            for (int j = 0; j < 4; j++) {
                int ch = j * 256 + tid;
                int r = ch >> 4, c = ch & 15;
                cp16(dstb + (a * 8704 + r * 136 + c * 8) * 2,
                     srcs[a] + (size_t)(tk0 + r) * HID_ + h * D_ + c * 8);
            }
        cp_commit();
    };

    const int ktmax = 2 * qt + 1;
    kvload(0);

    float acc[16][4] = {};
    float m_i[2] = {-1e30f, -1e30f};
    float l_i[2] = {0.f, 0.f};

    for (int kt = 0; kt <= ktmax; kt++) {
        if (kt + 1 <= ktmax) { kvload(kt + 1); cp_wait<1>(); }
        else cp_wait<0>();
        __syncthreads();

        const uint32_t stb = sb + (FA_ST + (kt & 1) * FA_ST) * 2;
        const bool active = (kt * 64 <= qt * 128 + wrow + 15);

        if (active) {
            float s[8][4] = {};
            #pragma unroll
            for (int ks = 0; ks < 8; ks++) {
                uint32_t qh[4], ql[4];
                {
                    int row = wrow + (lane & 15);
                    int seg = ks * 16 + 8 * (lane >> 4);
                    uint32_t addr = sb + (row * 136 + seg) * 2;
                    ldsm4(qh, addr);
                    ldsm4(ql, addr + 17408 * 2);
                }
                #pragma unroll
                for (int np = 0; np < 4; np++) {
                    uint32_t kh[4], kl[4];
                    int n = np * 16 + ((lane >> 4) << 3) + (lane & 7);
                    int seg = ks * 16 + 8 * ((lane >> 3) & 1);
                    uint32_t addr = stb + (n * 136 + seg) * 2;
                    ldsm4(kh, addr);
                    ldsm4(kl, addr + 8704 * 2);
                    #pragma unroll
                    for (int half_ = 0; half_ < 2; half_++) {
                        float* st_ = s[np * 2 + half_];
                        const uint32_t* bh2 = &kh[half_ * 2];
                        const uint32_t* bl2 = &kl[half_ * 2];
                        mma16816(st_, qh, bh2);
                        mma16816(st_, qh, bl2);
                        mma16816(st_, ql, bh2);
                    }
                }
            }

            const int rbase = qt * 128 + wrow + (lane >> 2);
            if (kt * 64 + 63 > qt * 128 + wrow) {
                #pragma unroll
                for (int j = 0; j < 8; j++)
                    #pragma unroll
                    for (int cc = 0; cc < 4; cc++) {
                        int colg = kt * 64 + j * 8 + (lane & 3) * 2 + (cc & 1);
                        int rowg = rbase + (cc >> 1) * 8;
                        if (colg > rowg) s[j][cc] = -1e30f;
                    }
            }
            #pragma unroll
            for (int j = 0; j < 8; j++)
                #pragma unroll
                for (int cc = 0; cc < 4; cc++) s[j][cc] *= SCALE_;

            #pragma unroll
            for (int hr = 0; hr < 2; hr++) {
                float rm = -1e30f;
                #pragma unroll
                for (int j = 0; j < 8; j++)
                    rm = fmaxf(rm, fmaxf(s[j][hr * 2], s[j][hr * 2 + 1]));
                rm = fmaxf(rm, __shfl_xor_sync(0xffffffffu, rm, 1));
                rm = fmaxf(rm, __shfl_xor_sync(0xffffffffu, rm, 2));
                float nm  = fmaxf(m_i[hr], rm);
                float fac = __expf(m_i[hr] - nm);
                m_i[hr] = nm;
                float rs = 0.f;
                #pragma unroll
                for (int j = 0; j < 8; j++) {
                    float p0 = __expf(s[j][hr * 2]     - nm);
                    float p1 = __expf(s[j][hr * 2 + 1] - nm);
                    s[j][hr * 2]     = p0;
                    s[j][hr * 2 + 1] = p1;
                    rs += p0 + p1;
                }
                rs += __shfl_xor_sync(0xffffffffu, rs, 1);
                rs += __shfl_xor_sync(0xffffffffu, rs, 2);
                l_i[hr] = l_i[hr] * fac + rs;
                #pragma unroll
                for (int nt = 0; nt < 16; nt++) {
                    acc[nt][hr * 2]     *= fac;
                    acc[nt][hr * 2 + 1] *= fac;
                }
            }

            uint32_t aH[4][4], aL[4][4];
            #pragma unroll
            for (int ks = 0; ks < 4; ks++) {
                #pragma unroll
                for (int half_ = 0; half_ < 2; half_++) {
                    const float* sj = s[ks * 2 + half_];
                    #pragma unroll
                    for (int rr = 0; rr < 2; rr++) {
                        float x0 = sj[rr * 2], x1 = sj[rr * 2 + 1];
                        __half h0 = __float2half_rn(x0), h1 = __float2half_rn(x1);
                        aH[ks][half_ * 2 + rr] = packh2(x0, x1);
                        aL[ks][half_ * 2 + rr] = packh2(x0 - __half2float(h0),
                                                        x1 - __half2float(h1));
                    }
                }
            }

            #pragma unroll
            for (int ks = 0; ks < 4; ks++) {
                #pragma unroll
                for (int ntp = 0; ntp < 8; ntp++) {
                    uint32_t vh[4], vl[4];
                    int kr = ks * 16 + (lane & 7) + 8 * ((lane >> 3) & 1);
                    int nc = ntp * 16 + 8 * (lane >> 4);
                    uint32_t addr = stb + (17408 + kr * 136 + nc) * 2;
                    ldsm4t(vh, addr);
                    ldsm4t(vl, addr + 8704 * 2);
                    #pragma unroll
                    for (int half_ = 0; half_ < 2; half_++) {
                        float* ot = acc[ntp * 2 + half_];
                        const uint32_t* bh2 = &vh[half_ * 2];
                        const uint32_t* bl2 = &vl[half_ * 2];
                        mma16816(ot, aH[ks], bh2);
                        mma16816(ot, aH[ks], bl2);
                        mma16816(ot, aL[ks], bh2);
                    }
                }
            }
        }
        __syncthreads();
    }

    float inv0 = 1.0f / l_i[0], inv1 = 1.0f / l_i[1];
    #pragma unroll
    for (int nt = 0; nt < 16; nt++) {
        float o0 = acc[nt][0] * inv0, o1 = acc[nt][1] * inv0;
        float o2 = acc[nt][2] * inv1, o3 = acc[nt][3] * inv1;
        size_t col = (size_t)h * D_ + nt * 8 + (lane & 3) * 2;
        size_t r0 = (size_t)(t0 + wrow + (lane >> 2)) * HID_ + col;
        size_t r1 = r0 + 8 * HID_;
        *(uint32_t*)(g_Ah + r0) = packh2(o0, o1);
        *(uint32_t*)(g_Ah + r1) = packh2(o2, o3);
    }
}

// ---------------------------------------------------------------------------
// Launch
// ---------------------------------------------------------------------------
extern "C" void kernel_launch(void* const* d_in, const int* in_sizes, int n_in,
                              void* d_out, int out_size)
{
    const float* hidden = (const float*)d_in[0];
    const float* cosT   = (const float*)d_in[1];
    const float* sinT   = (const float*)d_in[2];
    const float* w_qkv  = (const float*)d_in[3];
    const float* w_o    = (const float*)d_in[4];

    float* out = (float*)d_out;
    float* kc  = out + (size_t)T_ * HID_;
    float* vc  = kc + (size_t)T_ * HID_;

    float* qkvp = nullptr;
    __half *ahp = nullptr, *bhp = nullptr, *blp = nullptr;
    cudaGetSymbolAddress((void**)&qkvp, g_qkv);
    cudaGetSymbolAddress((void**)&ahp, g_Ah);
    cudaGetSymbolAddress((void**)&bhp, g_Bh);
    cudaGetSymbolAddress((void**)&blp, g_Bl);

    cudaFuncSetAttribute(hgemm_kernel, cudaFuncAttributeMaxDynamicSharedMemorySize,
                         G_SMEM);
    cudaFuncSetAttribute(fattn_kernel, cudaFuncAttributeMaxDynamicSharedMemorySize,
                         FA_SMEM_BYTES);

    // 1) convert hidden (hi only) + w_qkv (hi/lo, transposed)
    convH_kernel<<<(int)((size_t)T_ * HID_ / 8 / 256), 256>>>(hidden, ahp);
    convT_kernel<<<dim3(HID_ / 32, 3 * HID_ / 32), 256>>>(w_qkv, bhp, blp,
                                                          HID_, 3 * HID_);
    // 2) QKV GEMM (2-term) -> g_qkv fp32
    hgemm_kernel<<<dim3(T_ / 128, 3 * HID_ / 128), 128, G_SMEM>>>(
        ahp, bhp, blp, qkvp, 3 * HID_, HID_);
    // 3) RoPE + caches + fp16 attention operands
    rope_cache_kernel<<<T_ * H_, 64>>>(cosT, sinT, kc, vc);
    // 4) flash attention (3-term mma.sync) -> ctx fp16 into g_Ah
    fattn_kernel<<<dim3(S_ / 128, H_, B_), 256, FA_SMEM_BYTES>>>();
    // 5) convert w_o, output projection (2-term) -> out
    convT_kernel<<<dim3(HID_ / 32, HID_ / 32), 256>>>(w_o, bhp, blp, HID_, HID_);
    hgemm_kernel<<<dim3(T_ / 128, HID_ / 128), 128, G_SMEM>>>(
        ahp, bhp, blp, out, HID_, HID_);
}